// round 1
// baseline (speedup 1.0000x reference)
#include <cuda_runtime.h>
#include <cstdint>

#define BSZ   8
#define Hd    128
#define Ld    4096
#define LF    2049
#define NCOL  (BSZ*LF)      /* 16392 */
#define NCOLP 16448         /* padded to multiple of 64 */

// ---------------- scratch (device globals: allocation-free) ----------------
__device__ float2 g_twH[128];
__device__ float2 g_tw[2048];
__device__ float2 g_Bt[128*128];        // B~ [p][m]
__device__ float2 g_E [128*256];        // [ C~ | D~ ]  row stride 256
__device__ float2 g_T [128*128];        // scratch D*F
__device__ float2 g_Z [256*NCOLP];      // rows 0..127: W,  rows 128..255: Uhat
__device__ float2 g_Ys[128*NCOLP];      // spectral output

__device__ __forceinline__ float2 cmulf(float2 a, float2 b) {
    return make_float2(a.x*b.x - a.y*b.y, a.x*b.y + a.y*b.x);
}

// ---------------- setup: twiddles + folded matrices ----------------
__global__ void k_setup_tw() {
    int k = blockIdx.x*blockDim.x + threadIdx.x;
    if (k < 2048) { float s,c; sincospif(-(float)k/2048.0f,&s,&c); g_tw[k]=make_float2(c,s); }
    if (k < 128)  { float s,c; sincospif(-(float)k/64.0f,  &s,&c); g_twH[k]=make_float2(c,s); }
}

// bx 0..127: Bt rows p ; bx 128..255: C~ rows n ; bx 256..383: T rows h
__global__ void k_fold1(const float* __restrict__ C2, const float* __restrict__ Bb2,
                        const float* __restrict__ Dm) {
    int bx = blockIdx.x, t = threadIdx.x;
    if (bx < 128) {
        int p = bx, m = t;
        float2 acc = make_float2(0.f,0.f);
        for (int q = 0; q < 128; q++) {
            float2 w = g_twH[(q*m)&127];
            float br = Bb2[(p*128+q)*2], bi = Bb2[(p*128+q)*2+1];
            acc.x += br*w.x - bi*w.y;
            acc.y += br*w.y + bi*w.x;
        }
        g_Bt[p*128+m] = acc;
    } else if (bx < 256) {
        int n = bx-128, p = t;
        float2 acc = make_float2(0.f,0.f);
        for (int h = 0; h < 128; h++) {
            float2 w = g_twH[(n*h)&127]; w.y = -w.y;   // conj
            float cr = C2[(h*128+p)*2], ci = C2[(h*128+p)*2+1];
            acc.x += cr*w.x - ci*w.y;
            acc.y += cr*w.y + ci*w.x;
        }
        g_E[n*256 + p] = make_float2(acc.x*(1.0f/128.0f), acc.y*(1.0f/128.0f));
    } else {
        int h = bx-256, m = t;
        float2 acc = make_float2(0.f,0.f);
        for (int q = 0; q < 128; q++) {
            float2 w = g_twH[(q*m)&127];
            float d = Dm[h*128+q];
            acc.x += d*w.x; acc.y += d*w.y;
        }
        g_T[h*128+m] = acc;
    }
}

__global__ void k_fold2() {   // D~ = F* T / H  -> E[:,128:256]
    int n = blockIdx.x, m = threadIdx.x;
    float2 acc = make_float2(0.f,0.f);
    for (int h = 0; h < 128; h++) {
        float2 w = g_twH[(n*h)&127]; w.y = -w.y;   // conj
        float2 tv = g_T[h*128+m];
        acc.x += tv.x*w.x - tv.y*w.y;
        acc.y += tv.x*w.y + tv.y*w.x;
    }
    g_E[n*256 + 128 + m] = make_float2(acc.x*(1.0f/128.0f), acc.y*(1.0f/128.0f));
}

// ---------------- Stockham radix-2, N=4096, auto-sort, result ends in sa ----
__device__ __forceinline__ void stockham12(float2* sa, float2* sb, const float2* tw, bool inv) {
    float2* src = sa; float2* dst = sb;
    #pragma unroll 1
    for (int st = 0; st < 12; st++) {
        int nh = 2048 >> st;               // n/2 with n = 4096>>st
        int smask = (1<<st) - 1;
        for (int idx = threadIdx.x; idx < 2048; idx += blockDim.x) {
            int p = idx >> st;
            int q = idx & smask;
            float2 w = tw[p << st];
            if (inv) w.y = -w.y;
            float2 a = src[q + (p<<st)];
            float2 b = src[q + ((p+nh)<<st)];
            float2 sum = make_float2(a.x+b.x, a.y+b.y);
            float2 dif = make_float2(a.x-b.x, a.y-b.y);
            dst[q + ((2*p)<<st)]   = sum;
            dst[q + ((2*p+1)<<st)] = cmulf(dif, w);
        }
        __syncthreads();
        float2* tmp = src; src = dst; dst = tmp;
    }
}

// ---------------- forward: 2 real rows -> one cfft -> unpack into g_Z -------
__global__ void __launch_bounds__(512) k_fft_fwd(const float* __restrict__ u) {
    extern __shared__ float2 sm[];
    float2* sa = sm; float2* sb = sm+4096; float2* tw = sm+8192;
    int r0 = blockIdx.x*2;
    int b = r0 >> 7, h0 = r0 & 127;
    const float* u0 = u + (size_t)r0*Ld;
    for (int t = threadIdx.x; t < Ld; t += blockDim.x)
        sa[t] = make_float2(u0[t], u0[t+Ld]);
    for (int k = threadIdx.x; k < 2048; k += blockDim.x) tw[k] = g_tw[k];
    __syncthreads();
    stockham12(sa, sb, tw, false);
    float2* out0 = g_Z + (size_t)(128+h0)*NCOLP + b*LF;
    for (int k = threadIdx.x; k < LF; k += blockDim.x) {
        float2 zk = sa[k];
        float2 zn = sa[(4096-k)&4095];
        // X1 = (Z[k]+conj(Z[N-k]))/2 ; X2 = -i(Z[k]-conj(Z[N-k]))/2
        out0[k]       = make_float2(0.5f*(zk.x+zn.x), 0.5f*(zk.y-zn.y));
        out0[NCOLP+k] = make_float2(0.5f*(zk.y+zn.y), 0.5f*(zn.x-zk.x));
    }
}

// ---------------- complex SGEMM 128 x KDIM x NCOLP --------------------------
// MODE 0: W = Kcauchy ⊙ (Bt · Uhat)   (KDIM=128)
// MODE 1: Ys = [C~|D~] · [W;Uhat]     (KDIM=256)
template<int MODE>
__global__ void __launch_bounds__(256) k_cgemm(const float* __restrict__ Lam) {
    constexpr int KDIM = (MODE==0) ? 128 : 256;
    const float2* A  = (MODE==0) ? g_Bt : g_E;
    const float2* Bm = (MODE==0) ? (g_Z + (size_t)128*NCOLP) : g_Z;
    float2*       Cc = (MODE==0) ? g_Z : g_Ys;

    __shared__ float2 As[16][65];   // [k][m], padded
    __shared__ float2 Bs[16][64];   // [k][n]

    int row0 = blockIdx.y*64, col0 = blockIdx.x*64;
    int tid = threadIdx.x;
    int tx = tid & 15, ty = tid >> 4;
    int lk = tid & 15, li = tid >> 4;
    int bj = tid & 63, bk = tid >> 6;

    float2 acc[4][4];
    #pragma unroll
    for (int r=0;r<4;r++)
        #pragma unroll
        for (int c=0;c<4;c++) acc[r][c]=make_float2(0.f,0.f);

    for (int k0 = 0; k0 < KDIM; k0 += 16) {
        #pragma unroll
        for (int r=0;r<4;r++)
            As[lk][li + r*16] = A[(size_t)(row0+li+r*16)*KDIM + k0 + lk];
        #pragma unroll
        for (int r=0;r<4;r++)
            Bs[bk + r*4][bj] = Bm[(size_t)(k0+bk+r*4)*NCOLP + col0 + bj];
        __syncthreads();
        #pragma unroll
        for (int kk=0; kk<16; kk++) {
            float2 a[4], bb[4];
            #pragma unroll
            for (int r=0;r<4;r++) a[r]  = As[kk][ty + r*16];
            #pragma unroll
            for (int c=0;c<4;c++) bb[c] = Bs[kk][tx + c*16];
            #pragma unroll
            for (int r=0;r<4;r++)
                #pragma unroll
                for (int c=0;c<4;c++) {
                    acc[r][c].x = fmaf( a[r].x, bb[c].x, acc[r][c].x);
                    acc[r][c].x = fmaf(-a[r].y, bb[c].y, acc[r][c].x);
                    acc[r][c].y = fmaf( a[r].x, bb[c].y, acc[r][c].y);
                    acc[r][c].y = fmaf( a[r].y, bb[c].x, acc[r][c].y);
                }
        }
        __syncthreads();
    }
    #pragma unroll
    for (int r=0;r<4;r++) {
        int row = row0 + ty + r*16;
        float lre = 0.f, lim = 0.f;
        if (MODE==0) { lre = Lam[2*row]; lim = Lam[2*row+1]; }
        #pragma unroll
        for (int c=0;c<4;c++) {
            int j = col0 + tx + c*16;
            float2 v = acc[r][c];
            if (MODE==0) {
                int l = j % 2049;                         // freq index
                float omega = 1.5339807878856412e-3f * (float)l;  // 2*pi/4096 * l
                float dre = -lre, dim = omega - lim;      // i*w - lambda
                float inv = 1.0f/(dre*dre + dim*dim);
                float kre = dre*inv, kim = -dim*inv;      // 1/(iw - lambda)
                v = make_float2(v.x*kre - v.y*kim, v.x*kim + v.y*kre);
            }
            Cc[(size_t)row*NCOLP + j] = v;
        }
    }
}

// ---------------- inverse: pack 2 Hermitian spectra -> icfft -> gelu --------
__global__ void __launch_bounds__(512) k_fft_inv(float* __restrict__ out) {
    extern __shared__ float2 sm[];
    float2* sa = sm; float2* sb = sm+4096; float2* tw = sm+8192;
    int r0 = blockIdx.x*2;
    int b = r0 >> 7, h0 = r0 & 127;
    const float2* in0 = g_Ys + (size_t)h0*NCOLP + b*LF;
    for (int k = threadIdx.x; k < LF; k += blockDim.x) {
        float2 y1 = in0[k];
        float2 y2 = in0[NCOLP+k];
        if (k == 0 || k == 2048) { y1.y = 0.f; y2.y = 0.f; }  // irfft drops Im at DC/Nyquist
        sa[k] = make_float2(y1.x - y2.y, y1.y + y2.x);         // z = y1 + i*y2
        if (k > 0 && k < 2048)
            sa[4096-k] = make_float2(y1.x + y2.y, y2.x - y1.y); // conj(y1) + i*conj(y2)
    }
    for (int k = threadIdx.x; k < 2048; k += blockDim.x) tw[k] = g_tw[k];
    __syncthreads();
    stockham12(sa, sb, tw, true);
    float* o0 = out + (size_t)r0*Ld;
    const float sc = 1.0f/4096.0f;
    for (int t = threadIdx.x; t < Ld; t += blockDim.x) {
        float v0 = sa[t].x*sc, v1 = sa[t].y*sc;
        o0[t]    = 0.5f*v0*(1.0f + erff(v0*0.70710678118654752f));
        o0[t+Ld] = 0.5f*v1*(1.0f + erff(v1*0.70710678118654752f));
    }
}

// ---------------- launch ----------------------------------------------------
extern "C" void kernel_launch(void* const* d_in, const int* in_sizes, int n_in,
                              void* d_out, int out_size) {
    (void)in_sizes; (void)n_in; (void)out_size;
    const float* u   = (const float*)d_in[0];
    const float* C2  = (const float*)d_in[1];
    const float* Bb2 = (const float*)d_in[2];
    const float* Dm  = (const float*)d_in[3];
    const float* Lam = (const float*)d_in[4];
    float* out = (float*)d_out;

    const int smem = 10240 * (int)sizeof(float2);   // 80 KB: sa + sb + tw
    cudaFuncSetAttribute(k_fft_fwd, cudaFuncAttributeMaxDynamicSharedMemorySize, smem);
    cudaFuncSetAttribute(k_fft_inv, cudaFuncAttributeMaxDynamicSharedMemorySize, smem);

    k_setup_tw<<<2, 1024>>>();
    k_fold1<<<384, 128>>>(C2, Bb2, Dm);
    k_fold2<<<128, 128>>>();
    k_fft_fwd<<<512, 512, smem>>>(u);
    k_cgemm<0><<<dim3(NCOLP/64, 2), 256>>>(Lam);
    k_cgemm<1><<<dim3(NCOLP/64, 2), 256>>>(nullptr);
    k_fft_inv<<<512, 512, smem>>>(out);
}

// round 2
// speedup vs baseline: 1.2633x; 1.2633x over previous
#include <cuda_runtime.h>
#include <cuda_bf16.h>
#include <cstdint>

#define BSZ   8
#define Hd    128
#define Ld    4096
#define LF    2049
#define NCOL  (BSZ*LF)      /* 16392 */
#define NCOLP 16512         /* multiple of 128 */

// ---------------- scratch (device globals: allocation-free) ----------------
__device__ float2 g_twH[128];
__device__ float2 g_tw[2048];
__device__ float2 g_Bt[128*128];        // B~ [p][m]
__device__ float2 g_E [128*256];        // [ C~ | D~ ]  row stride 256
__device__ float2 g_T [128*128];        // scratch D*F
__device__ float2 g_Z [256*NCOLP];      // rows 0..127: W,  rows 128..255: Uhat
__device__ float2 g_Ys[128*NCOLP];      // spectral output

__device__ __forceinline__ float2 cmulf(float2 a, float2 b) {
    return make_float2(a.x*b.x - a.y*b.y, a.x*b.y + a.y*b.x);
}

// ---------------- setup: twiddles + folded matrices ----------------
__global__ void k_setup_tw() {
    int k = blockIdx.x*blockDim.x + threadIdx.x;
    if (k < 2048) { float s,c; sincospif(-(float)k/2048.0f,&s,&c); g_tw[k]=make_float2(c,s); }
    if (k < 128)  { float s,c; sincospif(-(float)k/64.0f,  &s,&c); g_twH[k]=make_float2(c,s); }
}

__global__ void k_fold1(const float* __restrict__ C2, const float* __restrict__ Bb2,
                        const float* __restrict__ Dm) {
    int bx = blockIdx.x, t = threadIdx.x;
    if (bx < 128) {
        int p = bx, m = t;
        float2 acc = make_float2(0.f,0.f);
        for (int q = 0; q < 128; q++) {
            float2 w = g_twH[(q*m)&127];
            float br = Bb2[(p*128+q)*2], bi = Bb2[(p*128+q)*2+1];
            acc.x += br*w.x - bi*w.y;
            acc.y += br*w.y + bi*w.x;
        }
        g_Bt[p*128+m] = acc;
    } else if (bx < 256) {
        int n = bx-128, p = t;
        float2 acc = make_float2(0.f,0.f);
        for (int h = 0; h < 128; h++) {
            float2 w = g_twH[(n*h)&127]; w.y = -w.y;   // conj
            float cr = C2[(h*128+p)*2], ci = C2[(h*128+p)*2+1];
            acc.x += cr*w.x - ci*w.y;
            acc.y += cr*w.y + ci*w.x;
        }
        g_E[n*256 + p] = make_float2(acc.x*(1.0f/128.0f), acc.y*(1.0f/128.0f));
    } else {
        int h = bx-256, m = t;
        float2 acc = make_float2(0.f,0.f);
        for (int q = 0; q < 128; q++) {
            float2 w = g_twH[(q*m)&127];
            float d = Dm[h*128+q];
            acc.x += d*w.x; acc.y += d*w.y;
        }
        g_T[h*128+m] = acc;
    }
}

__global__ void k_fold2() {   // D~ = F* T / H  -> E[:,128:256]
    int n = blockIdx.x, m = threadIdx.x;
    float2 acc = make_float2(0.f,0.f);
    for (int h = 0; h < 128; h++) {
        float2 w = g_twH[(n*h)&127]; w.y = -w.y;   // conj
        float2 tv = g_T[h*128+m];
        acc.x += tv.x*w.x - tv.y*w.y;
        acc.y += tv.x*w.y + tv.y*w.x;
    }
    g_E[n*256 + 128 + m] = make_float2(acc.x*(1.0f/128.0f), acc.y*(1.0f/128.0f));
}

// ---------------- Stockham radix-2, N=4096 ----------------------------------
__device__ __forceinline__ void stockham12(float2* sa, float2* sb, const float2* tw, bool inv) {
    float2* src = sa; float2* dst = sb;
    #pragma unroll 1
    for (int st = 0; st < 12; st++) {
        int nh = 2048 >> st;
        int smask = (1<<st) - 1;
        for (int idx = threadIdx.x; idx < 2048; idx += blockDim.x) {
            int p = idx >> st;
            int q = idx & smask;
            float2 w = tw[p << st];
            if (inv) w.y = -w.y;
            float2 a = src[q + (p<<st)];
            float2 b = src[q + ((p+nh)<<st)];
            float2 sum = make_float2(a.x+b.x, a.y+b.y);
            float2 dif = make_float2(a.x-b.x, a.y-b.y);
            dst[q + ((2*p)<<st)]   = sum;
            dst[q + ((2*p+1)<<st)] = cmulf(dif, w);
        }
        __syncthreads();
        float2* tmp = src; src = dst; dst = tmp;
    }
}

__global__ void __launch_bounds__(512) k_fft_fwd(const float* __restrict__ u) {
    extern __shared__ float2 sm[];
    float2* sa = sm; float2* sb = sm+4096; float2* tw = sm+8192;
    int r0 = blockIdx.x*2;
    int b = r0 >> 7, h0 = r0 & 127;
    const float* u0 = u + (size_t)r0*Ld;
    for (int t = threadIdx.x; t < Ld; t += blockDim.x)
        sa[t] = make_float2(u0[t], u0[t+Ld]);
    for (int k = threadIdx.x; k < 2048; k += blockDim.x) tw[k] = g_tw[k];
    __syncthreads();
    stockham12(sa, sb, tw, false);
    float2* out0 = g_Z + (size_t)(128+h0)*NCOLP + b*LF;
    for (int k = threadIdx.x; k < LF; k += blockDim.x) {
        float2 zk = sa[k];
        float2 zn = sa[(4096-k)&4095];
        out0[k]       = make_float2(0.5f*(zk.x+zn.x), 0.5f*(zk.y-zn.y));
        out0[NCOLP+k] = make_float2(0.5f*(zk.y+zn.y), 0.5f*(zn.x-zk.x));
    }
}

// ---------------- tensor-core complex GEMM ----------------------------------
// Split-fp32: a = hi + lo (bf16 each); keep hi*hi + hi*lo + lo*hi.
// Complex: Cr = Ar*Br + (-Ai)*Bi ; Ci = Ar*Bi + Ai*Br  (A planes: ArH ArL AiH AiL AnH AnL)
// B planes: 0=BrH 1=BrL 2=BiH 3=BiL.
// CTA tile 64(M) x 128(N), K-step 32, 8 warps (2M x 4N), warp tile 32x32.

#define AS_STRIDE 40
#define AS_PLANE  (64*AS_STRIDE)        // 2560 bf16
#define BS_PLANE  (128*AS_STRIDE)       // 5120 bf16
#define SMEM_BF16 (6*AS_PLANE + 4*BS_PLANE)   // 35840 bf16 = 71680 B

__device__ __forceinline__ uint32_t cvta_s(const void* p) {
    return (uint32_t)__cvta_generic_to_shared(p);
}
__device__ __forceinline__ void ldsm_x4(uint32_t& r0, uint32_t& r1, uint32_t& r2, uint32_t& r3,
                                        uint32_t addr) {
    asm volatile("ldmatrix.sync.aligned.m8n8.x4.shared.b16 {%0,%1,%2,%3}, [%4];"
                 : "=r"(r0), "=r"(r1), "=r"(r2), "=r"(r3) : "r"(addr));
}
__device__ __forceinline__ void mma_bf16(float* c, const uint32_t* a, const uint32_t* b) {
    asm volatile("mma.sync.aligned.m16n8k16.row.col.f32.bf16.bf16.f32 "
                 "{%0,%1,%2,%3}, {%4,%5,%6,%7}, {%8,%9}, {%0,%1,%2,%3};"
                 : "+f"(c[0]), "+f"(c[1]), "+f"(c[2]), "+f"(c[3])
                 : "r"(a[0]), "r"(a[1]), "r"(a[2]), "r"(a[3]), "r"(b[0]), "r"(b[1]));
}
__device__ __forceinline__ void split2(float v, __nv_bfloat16& h, __nv_bfloat16& l) {
    h = __float2bfloat16(v);
    l = __float2bfloat16(v - __bfloat162float(h));
}

template<int MODE>
__global__ void __launch_bounds__(256) k_cgemm_tc(const float* __restrict__ Lam) {
    constexpr int KDIM = (MODE==0) ? 128 : 256;
    const float2* A  = (MODE==0) ? g_Bt : g_E;
    const float2* Bm = (MODE==0) ? (g_Z + (size_t)128*NCOLP) : g_Z;
    float2*       Cc = (MODE==0) ? g_Z : g_Ys;

    extern __shared__ __nv_bfloat16 smem[];
    __nv_bfloat16* As = smem;                       // 6 planes [m][k]
    __nv_bfloat16* Bs = smem + 6*AS_PLANE;          // 4 planes [n][k]

    const int tid  = threadIdx.x;
    const int warp = tid >> 5, lane = tid & 31;
    const int wm = warp & 1, wn = warp >> 1;
    const int row0 = blockIdx.y*64, col0 = blockIdx.x*128;

    // ldmatrix per-lane offsets
    const int g  = lane >> 3, tr = lane & 7;
    const int a_m = ((g & 1) << 3) + tr, a_k = (g >> 1) << 3;      // A groups
    const int b_n = ((g >> 1) << 3) + tr, b_k = (g & 1) << 3;      // B groups

    float acc_r[2][4][4], acc_i[2][4][4];
    #pragma unroll
    for (int mf=0;mf<2;mf++)
        #pragma unroll
        for (int nf=0;nf<4;nf++)
            #pragma unroll
            for (int r=0;r<4;r++) { acc_r[mf][nf][r]=0.f; acc_i[mf][nf][r]=0.f; }

    for (int k0 = 0; k0 < KDIM; k0 += 32) {
        // ---- stage A: 64x32 complex -> 6 bf16 planes
        #pragma unroll
        for (int i = 0; i < 8; i++) {
            int idx = tid + i*256;
            int m = idx >> 5, k = idx & 31;
            float2 av = A[(size_t)(row0+m)*KDIM + k0 + k];
            int off = m*AS_STRIDE + k;
            __nv_bfloat16 h, l;
            split2(av.x, h, l);  As[0*AS_PLANE+off]=h; As[1*AS_PLANE+off]=l;
            split2(av.y, h, l);  As[2*AS_PLANE+off]=h; As[3*AS_PLANE+off]=l;
            split2(-av.y, h, l); As[4*AS_PLANE+off]=h; As[5*AS_PLANE+off]=l;
        }
        // ---- stage B: 32x128 complex -> 4 bf16 planes, transposed [n][k]
        #pragma unroll
        for (int i = 0; i < 16; i++) {
            int idx = tid + i*256;
            int n = idx & 127, kb = idx >> 7;
            float2 bv = Bm[(size_t)(k0+kb)*NCOLP + col0 + n];
            int off = n*AS_STRIDE + kb;
            __nv_bfloat16 h, l;
            split2(bv.x, h, l);  Bs[0*BS_PLANE+off]=h; Bs[1*BS_PLANE+off]=l;
            split2(bv.y, h, l);  Bs[2*BS_PLANE+off]=h; Bs[3*BS_PLANE+off]=l;
        }
        __syncthreads();

        #pragma unroll
        for (int kk = 0; kk < 32; kk += 16) {
            // load all B fragments: b[plane][nf][khalf]
            uint32_t b[4][4][2];
            #pragma unroll
            for (int q = 0; q < 4; q++)
                #pragma unroll
                for (int np = 0; np < 2; np++) {
                    int nbase = wn*32 + np*16;
                    uint32_t addr = cvta_s(&Bs[q*BS_PLANE + (nbase + b_n)*AS_STRIDE + kk + b_k]);
                    ldsm_x4(b[q][2*np][0], b[q][2*np][1], b[q][2*np+1][0], b[q][2*np+1][1], addr);
                }
            // plane-by-plane A loads + mma
            #pragma unroll
            for (int p = 0; p < 6; p++) {
                uint32_t a[2][4];
                #pragma unroll
                for (int mf = 0; mf < 2; mf++) {
                    int mbase = wm*32 + mf*16;
                    uint32_t addr = cvta_s(&As[p*AS_PLANE + (mbase + a_m)*AS_STRIDE + kk + a_k]);
                    ldsm_x4(a[mf][0], a[mf][1], a[mf][2], a[mf][3], addr);
                }
                #pragma unroll
                for (int mf = 0; mf < 2; mf++)
                    #pragma unroll
                    for (int nf = 0; nf < 4; nf++) {
                        if (p == 0) {                       // ArH
                            mma_bf16(acc_r[mf][nf], a[mf], b[0][nf]);
                            mma_bf16(acc_r[mf][nf], a[mf], b[1][nf]);
                            mma_bf16(acc_i[mf][nf], a[mf], b[2][nf]);
                            mma_bf16(acc_i[mf][nf], a[mf], b[3][nf]);
                        } else if (p == 1) {                // ArL
                            mma_bf16(acc_r[mf][nf], a[mf], b[0][nf]);
                            mma_bf16(acc_i[mf][nf], a[mf], b[2][nf]);
                        } else if (p == 2) {                // AiH
                            mma_bf16(acc_i[mf][nf], a[mf], b[0][nf]);
                            mma_bf16(acc_i[mf][nf], a[mf], b[1][nf]);
                        } else if (p == 3) {                // AiL
                            mma_bf16(acc_i[mf][nf], a[mf], b[0][nf]);
                        } else if (p == 4) {                // AnH = -AiH
                            mma_bf16(acc_r[mf][nf], a[mf], b[2][nf]);
                            mma_bf16(acc_r[mf][nf], a[mf], b[3][nf]);
                        } else {                            // AnL
                            mma_bf16(acc_r[mf][nf], a[mf], b[2][nf]);
                        }
                    }
            }
        }
        __syncthreads();
    }

    // ---- epilogue
    #pragma unroll
    for (int mf = 0; mf < 2; mf++) {
        #pragma unroll
        for (int h = 0; h < 2; h++) {
            int row = row0 + wm*32 + mf*16 + (lane>>2) + h*8;
            float lre = 0.f, lim = 0.f;
            if (MODE==0) { lre = Lam[2*row]; lim = Lam[2*row+1]; }
            #pragma unroll
            for (int nf = 0; nf < 4; nf++) {
                int col = col0 + wn*32 + nf*8 + (lane&3)*2;
                float vr0 = acc_r[mf][nf][h*2+0], vi0 = acc_i[mf][nf][h*2+0];
                float vr1 = acc_r[mf][nf][h*2+1], vi1 = acc_i[mf][nf][h*2+1];
                if (MODE==0) {
                    int l0 = col % 2049, l1 = (col+1) % 2049;
                    float om0 = 1.5339807878856412e-3f * (float)l0;
                    float om1 = 1.5339807878856412e-3f * (float)l1;
                    float dre = -lre;
                    float di0 = om0 - lim, di1 = om1 - lim;
                    float iv0 = 1.0f/(dre*dre + di0*di0);
                    float iv1 = 1.0f/(dre*dre + di1*di1);
                    float kr0 = dre*iv0, ki0 = -di0*iv0;
                    float kr1 = dre*iv1, ki1 = -di1*iv1;
                    float tr0 = vr0*kr0 - vi0*ki0, ti0 = vr0*ki0 + vi0*kr0;
                    float tr1 = vr1*kr1 - vi1*ki1, ti1 = vr1*ki1 + vi1*kr1;
                    vr0=tr0; vi0=ti0; vr1=tr1; vi1=ti1;
                }
                float4 o = make_float4(vr0, vi0, vr1, vi1);
                *reinterpret_cast<float4*>(&Cc[(size_t)row*NCOLP + col]) = o;
            }
        }
    }
}

// ---------------- inverse FFT + GELU ----------------------------------------
__global__ void __launch_bounds__(512) k_fft_inv(float* __restrict__ out) {
    extern __shared__ float2 sm[];
    float2* sa = sm; float2* sb = sm+4096; float2* tw = sm+8192;
    int r0 = blockIdx.x*2;
    int b = r0 >> 7, h0 = r0 & 127;
    const float2* in0 = g_Ys + (size_t)h0*NCOLP + b*LF;
    for (int k = threadIdx.x; k < LF; k += blockDim.x) {
        float2 y1 = in0[k];
        float2 y2 = in0[NCOLP+k];
        if (k == 0 || k == 2048) { y1.y = 0.f; y2.y = 0.f; }
        sa[k] = make_float2(y1.x - y2.y, y1.y + y2.x);
        if (k > 0 && k < 2048)
            sa[4096-k] = make_float2(y1.x + y2.y, y2.x - y1.y);
    }
    for (int k = threadIdx.x; k < 2048; k += blockDim.x) tw[k] = g_tw[k];
    __syncthreads();
    stockham12(sa, sb, tw, true);
    float* o0 = out + (size_t)r0*Ld;
    const float sc = 1.0f/4096.0f;
    for (int t = threadIdx.x; t < Ld; t += blockDim.x) {
        float v0 = sa[t].x*sc, v1 = sa[t].y*sc;
        o0[t]    = 0.5f*v0*(1.0f + erff(v0*0.70710678118654752f));
        o0[t+Ld] = 0.5f*v1*(1.0f + erff(v1*0.70710678118654752f));
    }
}

// ---------------- launch ----------------------------------------------------
extern "C" void kernel_launch(void* const* d_in, const int* in_sizes, int n_in,
                              void* d_out, int out_size) {
    (void)in_sizes; (void)n_in; (void)out_size;
    const float* u   = (const float*)d_in[0];
    const float* C2  = (const float*)d_in[1];
    const float* Bb2 = (const float*)d_in[2];
    const float* Dm  = (const float*)d_in[3];
    const float* Lam = (const float*)d_in[4];
    float* out = (float*)d_out;

    const int smem_fft = 10240 * (int)sizeof(float2);   // 80 KB
    cudaFuncSetAttribute(k_fft_fwd, cudaFuncAttributeMaxDynamicSharedMemorySize, smem_fft);
    cudaFuncSetAttribute(k_fft_inv, cudaFuncAttributeMaxDynamicSharedMemorySize, smem_fft);
    const int smem_gemm = SMEM_BF16 * 2;                // 71680 B
    cudaFuncSetAttribute(k_cgemm_tc<0>, cudaFuncAttributeMaxDynamicSharedMemorySize, smem_gemm);
    cudaFuncSetAttribute(k_cgemm_tc<1>, cudaFuncAttributeMaxDynamicSharedMemorySize, smem_gemm);

    k_setup_tw<<<2, 1024>>>();
    k_fold1<<<384, 128>>>(C2, Bb2, Dm);
    k_fold2<<<128, 128>>>();
    k_fft_fwd<<<512, 512, smem_fft>>>(u);
    k_cgemm_tc<0><<<dim3(NCOLP/128, 2), 256, smem_gemm>>>(Lam);
    k_cgemm_tc<1><<<dim3(NCOLP/128, 2), 256, smem_gemm>>>(nullptr);
    k_fft_inv<<<512, 512, smem_fft>>>(out);
}

// round 3
// speedup vs baseline: 1.4492x; 1.1472x over previous
#include <cuda_runtime.h>
#include <cuda_bf16.h>
#include <cstdint>

#define BSZ   8
#define Hd    128
#define Ld    4096
#define LF    2049
#define NCOL  (BSZ*LF)      /* 16392 */
#define NCOLP 16512         /* multiple of 128 */

// ---------------- scratch (device globals: allocation-free) ----------------
__device__ float2 g_twH[128];
__device__ float2 g_tw[2048];
__device__ float2 g_Bt[128*128];              // fp32 B~ [p][m]
__device__ float2 g_E [128*256];              // fp32 [C~|D~] row stride 256
__device__ float2 g_T [128*128];              // scratch
__device__ __nv_bfloat16 g_AB[6][128*128];    // split planes of B~
__device__ __nv_bfloat16 g_AE[6][128*256];    // split planes of [C~|D~]
__device__ __nv_bfloat16 g_Pb[4][256*NCOLP];  // B-operand planes: rows 0..127=W, 128..255=Uhat
__device__ float2 g_Ys[128*NCOLP];            // spectral output (fp32)

__device__ __forceinline__ float2 cmulf(float2 a, float2 b) {
    return make_float2(a.x*b.x - a.y*b.y, a.x*b.y + a.y*b.x);
}
__device__ __forceinline__ void split2(float v, __nv_bfloat16& h, __nv_bfloat16& l) {
    h = __float2bfloat16(v);
    l = __float2bfloat16(v - __bfloat162float(h));
}

// ---------------- setup ----------------
__global__ void k_setup_tw() {
    int k = blockIdx.x*blockDim.x + threadIdx.x;
    if (k < 2048) { float s,c; sincospif(-(float)k/2048.0f,&s,&c); g_tw[k]=make_float2(c,s); }
    if (k < 128)  { float s,c; sincospif(-(float)k/64.0f,  &s,&c); g_twH[k]=make_float2(c,s); }
}

__global__ void k_fold1(const float* __restrict__ C2, const float* __restrict__ Bb2,
                        const float* __restrict__ Dm) {
    int bx = blockIdx.x, t = threadIdx.x;
    if (bx < 128) {
        int p = bx, m = t;
        float2 acc = make_float2(0.f,0.f);
        for (int q = 0; q < 128; q++) {
            float2 w = g_twH[(q*m)&127];
            float br = Bb2[(p*128+q)*2], bi = Bb2[(p*128+q)*2+1];
            acc.x += br*w.x - bi*w.y;
            acc.y += br*w.y + bi*w.x;
        }
        g_Bt[p*128+m] = acc;
    } else if (bx < 256) {
        int n = bx-128, p = t;
        float2 acc = make_float2(0.f,0.f);
        for (int h = 0; h < 128; h++) {
            float2 w = g_twH[(n*h)&127]; w.y = -w.y;
            float cr = C2[(h*128+p)*2], ci = C2[(h*128+p)*2+1];
            acc.x += cr*w.x - ci*w.y;
            acc.y += cr*w.y + ci*w.x;
        }
        g_E[n*256 + p] = make_float2(acc.x*(1.0f/128.0f), acc.y*(1.0f/128.0f));
    } else {
        int h = bx-256, m = t;
        float2 acc = make_float2(0.f,0.f);
        for (int q = 0; q < 128; q++) {
            float2 w = g_twH[(q*m)&127];
            float d = Dm[h*128+q];
            acc.x += d*w.x; acc.y += d*w.y;
        }
        g_T[h*128+m] = acc;
    }
}

__global__ void k_fold2() {
    int n = blockIdx.x, m = threadIdx.x;
    float2 acc = make_float2(0.f,0.f);
    for (int h = 0; h < 128; h++) {
        float2 w = g_twH[(n*h)&127]; w.y = -w.y;
        float2 tv = g_T[h*128+m];
        acc.x += tv.x*w.x - tv.y*w.y;
        acc.y += tv.x*w.y + tv.y*w.x;
    }
    g_E[n*256 + 128 + m] = make_float2(acc.x*(1.0f/128.0f), acc.y*(1.0f/128.0f));
}

// split A matrices into bf16 planes (ArH ArL AiH AiL -AiH -AiL)
__global__ void k_splitA() {
    int idx = blockIdx.x*blockDim.x + threadIdx.x;
    __nv_bfloat16 h, l;
    if (idx < 128*128) {
        float2 v = g_Bt[idx];
        split2(v.x,h,l);  g_AB[0][idx]=h; g_AB[1][idx]=l;
        split2(v.y,h,l);  g_AB[2][idx]=h; g_AB[3][idx]=l;
        split2(-v.y,h,l); g_AB[4][idx]=h; g_AB[5][idx]=l;
    }
    int idx2 = idx - 128*128;
    if (idx2 >= 0 && idx2 < 128*256) {
        float2 v = g_E[idx2];
        split2(v.x,h,l);  g_AE[0][idx2]=h; g_AE[1][idx2]=l;
        split2(v.y,h,l);  g_AE[2][idx2]=h; g_AE[3][idx2]=l;
        split2(-v.y,h,l); g_AE[4][idx2]=h; g_AE[5][idx2]=l;
    }
}

// ---------------- Stockham radix-2, N=4096 ----------------------------------
__device__ __forceinline__ void stockham12(float2* sa, float2* sb, const float2* tw, bool inv) {
    float2* src = sa; float2* dst = sb;
    #pragma unroll 1
    for (int st = 0; st < 12; st++) {
        int nh = 2048 >> st;
        int smask = (1<<st) - 1;
        for (int idx = threadIdx.x; idx < 2048; idx += blockDim.x) {
            int p = idx >> st;
            int q = idx & smask;
            float2 w = tw[p << st];
            if (inv) w.y = -w.y;
            float2 a = src[q + (p<<st)];
            float2 b = src[q + ((p+nh)<<st)];
            float2 sum = make_float2(a.x+b.x, a.y+b.y);
            float2 dif = make_float2(a.x-b.x, a.y-b.y);
            dst[q + ((2*p)<<st)]   = sum;
            dst[q + ((2*p+1)<<st)] = cmulf(dif, w);
        }
        __syncthreads();
        float2* tmp = src; src = dst; dst = tmp;
    }
}

// forward FFT: writes Uhat straight into bf16 split planes (rows 128..255 of g_Pb)
__global__ void __launch_bounds__(512) k_fft_fwd(const float* __restrict__ u) {
    extern __shared__ float2 sm[];
    float2* sa = sm; float2* sb = sm+4096; float2* tw = sm+8192;
    int r0 = blockIdx.x*2;
    int b = r0 >> 7, h0 = r0 & 127;
    const float* u0 = u + (size_t)r0*Ld;
    for (int t = threadIdx.x; t < Ld; t += blockDim.x)
        sa[t] = make_float2(u0[t], u0[t+Ld]);
    for (int k = threadIdx.x; k < 2048; k += blockDim.x) tw[k] = g_tw[k];
    __syncthreads();
    stockham12(sa, sb, tw, false);
    size_t o1 = (size_t)(128+h0)*NCOLP + b*LF;
    size_t o2 = o1 + NCOLP;
    for (int k = threadIdx.x; k < LF; k += blockDim.x) {
        float2 zk = sa[k];
        float2 zn = sa[(4096-k)&4095];
        float2 x1 = make_float2(0.5f*(zk.x+zn.x), 0.5f*(zk.y-zn.y));
        float2 x2 = make_float2(0.5f*(zk.y+zn.y), 0.5f*(zn.x-zk.x));
        __nv_bfloat16 h, l;
        split2(x1.x,h,l); g_Pb[0][o1+k]=h; g_Pb[1][o1+k]=l;
        split2(x1.y,h,l); g_Pb[2][o1+k]=h; g_Pb[3][o1+k]=l;
        split2(x2.x,h,l); g_Pb[0][o2+k]=h; g_Pb[1][o2+k]=l;
        split2(x2.y,h,l); g_Pb[2][o2+k]=h; g_Pb[3][o2+k]=l;
    }
}

// ---------------- tensor-core complex GEMM, cp.async double-buffered --------
#define ASTR 40
#define APL  (64*ASTR)          // 2560 bf16 per A plane
#define BSTR 136
#define BPL  (32*BSTR)          // 4352 bf16 per B plane
#define BUF_BF16 (6*APL + 4*BPL)        // 32768 bf16 = 64 KB
#define GSMEM (2*BUF_BF16*2)            // bytes

__device__ __forceinline__ uint32_t cvta_s(const void* p) {
    return (uint32_t)__cvta_generic_to_shared(p);
}
__device__ __forceinline__ void cp16(uint32_t s, const void* g) {
    asm volatile("cp.async.cg.shared.global [%0], [%1], 16;" :: "r"(s), "l"(g));
}
__device__ __forceinline__ void cp_commit() { asm volatile("cp.async.commit_group;"); }
__device__ __forceinline__ void cp_wait1()  { asm volatile("cp.async.wait_group 1;"); }
__device__ __forceinline__ void ldsm_x4(uint32_t& r0, uint32_t& r1, uint32_t& r2, uint32_t& r3,
                                        uint32_t addr) {
    asm volatile("ldmatrix.sync.aligned.m8n8.x4.shared.b16 {%0,%1,%2,%3}, [%4];"
                 : "=r"(r0), "=r"(r1), "=r"(r2), "=r"(r3) : "r"(addr));
}
__device__ __forceinline__ void ldsm_x4t(uint32_t& r0, uint32_t& r1, uint32_t& r2, uint32_t& r3,
                                         uint32_t addr) {
    asm volatile("ldmatrix.sync.aligned.m8n8.x4.trans.shared.b16 {%0,%1,%2,%3}, [%4];"
                 : "=r"(r0), "=r"(r1), "=r"(r2), "=r"(r3) : "r"(addr));
}
__device__ __forceinline__ void mma_bf16(float* c, const uint32_t* a, const uint32_t* b) {
    asm volatile("mma.sync.aligned.m16n8k16.row.col.f32.bf16.bf16.f32 "
                 "{%0,%1,%2,%3}, {%4,%5,%6,%7}, {%8,%9}, {%0,%1,%2,%3};"
                 : "+f"(c[0]), "+f"(c[1]), "+f"(c[2]), "+f"(c[3])
                 : "r"(a[0]), "r"(a[1]), "r"(a[2]), "r"(a[3]), "r"(b[0]), "r"(b[1]));
}

// MODE0: W = K ⊙ (Bt·Uhat): A=g_AB (K=128), B rows 128.., out bf16 planes rows 0..127
// MODE1: Ys = [C~|D~]·[W;Uhat]: A=g_AE (K=256), B rows 0.., out g_Ys fp32
template<int MODE>
__global__ void __launch_bounds__(256) k_cgemm_tc(const float* __restrict__ Lam) {
    constexpr int KDIM  = (MODE==0) ? 128 : 256;
    constexpr int KITER = KDIM/32;
    constexpr int RBASE = (MODE==0) ? 128 : 0;
    const __nv_bfloat16* Apl = (MODE==0) ? g_AB[0] : g_AE[0];
    constexpr int APLANE_G = (MODE==0) ? 128*128 : 128*256;

    extern __shared__ __nv_bfloat16 smem[];

    const int tid  = threadIdx.x;
    const int warp = tid >> 5, lane = tid & 31;
    const int wm = warp & 1, wn = warp >> 1;
    const int row0 = blockIdx.y*64, col0 = blockIdx.x*128;

    const int l16 = lane & 15, lhi = (lane >> 4) << 3;

    float acc_r[2][4][4], acc_i[2][4][4];
    #pragma unroll
    for (int mf=0;mf<2;mf++)
        #pragma unroll
        for (int nf=0;nf<4;nf++)
            #pragma unroll
            for (int r=0;r<4;r++) { acc_r[mf][nf][r]=0.f; acc_i[mf][nf][r]=0.f; }

    // staging lambda (macro-style)
    auto stage = [&](int buf, int k0) {
        __nv_bfloat16* As = smem + buf*BUF_BF16;
        __nv_bfloat16* Bs = As + 6*APL;
        #pragma unroll
        for (int i = 0; i < 6; i++) {                 // A: 6 planes x 64 x 32
            int idx = tid + i*256;
            int pl = idx >> 8, rem = idx & 255;
            int m = rem >> 2, c = rem & 3;
            cp16(cvta_s(As + pl*APL + m*ASTR + c*8),
                 Apl + (size_t)pl*APLANE_G + (size_t)(row0+m)*KDIM + k0 + c*8);
        }
        #pragma unroll
        for (int i = 0; i < 8; i++) {                 // B: 4 planes x 32 x 128
            int idx = tid + i*256;
            int pl = idx >> 9, rem = idx & 511;
            int kr = rem >> 4, c = rem & 15;
            cp16(cvta_s(Bs + pl*BPL + kr*BSTR + c*8),
                 g_Pb[pl] + (size_t)(RBASE + k0 + kr)*NCOLP + col0 + c*8);
        }
    };

    stage(0, 0);
    cp_commit();

    int buf = 0;
    for (int it = 0; it < KITER; it++) {
        if (it+1 < KITER) stage(buf^1, (it+1)*32);
        cp_commit();
        cp_wait1();
        __syncthreads();

        const __nv_bfloat16* As = smem + buf*BUF_BF16;
        const __nv_bfloat16* Bs = As + 6*APL;

        #pragma unroll
        for (int kk = 0; kk < 32; kk += 16) {
            uint32_t b[4][4][2];
            #pragma unroll
            for (int q = 0; q < 4; q++)
                #pragma unroll
                for (int np = 0; np < 2; np++) {
                    uint32_t addr = cvta_s(Bs + q*BPL + (kk + l16)*BSTR
                                           + wn*32 + np*16 + lhi);
                    ldsm_x4t(b[q][2*np][0], b[q][2*np][1], b[q][2*np+1][0], b[q][2*np+1][1], addr);
                }
            #pragma unroll
            for (int p = 0; p < 6; p++) {
                uint32_t a[2][4];
                #pragma unroll
                for (int mf = 0; mf < 2; mf++) {
                    uint32_t addr = cvta_s(As + p*APL + (wm*32 + mf*16 + l16)*ASTR + kk + lhi);
                    ldsm_x4(a[mf][0], a[mf][1], a[mf][2], a[mf][3], addr);
                }
                #pragma unroll
                for (int mf = 0; mf < 2; mf++)
                    #pragma unroll
                    for (int nf = 0; nf < 4; nf++) {
                        if (p == 0) {
                            mma_bf16(acc_r[mf][nf], a[mf], b[0][nf]);
                            mma_bf16(acc_r[mf][nf], a[mf], b[1][nf]);
                            mma_bf16(acc_i[mf][nf], a[mf], b[2][nf]);
                            mma_bf16(acc_i[mf][nf], a[mf], b[3][nf]);
                        } else if (p == 1) {
                            mma_bf16(acc_r[mf][nf], a[mf], b[0][nf]);
                            mma_bf16(acc_i[mf][nf], a[mf], b[2][nf]);
                        } else if (p == 2) {
                            mma_bf16(acc_i[mf][nf], a[mf], b[0][nf]);
                            mma_bf16(acc_i[mf][nf], a[mf], b[1][nf]);
                        } else if (p == 3) {
                            mma_bf16(acc_i[mf][nf], a[mf], b[0][nf]);
                        } else if (p == 4) {
                            mma_bf16(acc_r[mf][nf], a[mf], b[2][nf]);
                            mma_bf16(acc_r[mf][nf], a[mf], b[3][nf]);
                        } else {
                            mma_bf16(acc_r[mf][nf], a[mf], b[2][nf]);
                        }
                    }
            }
        }
        buf ^= 1;
        __syncthreads();
    }

    // ---- epilogue
    #pragma unroll
    for (int mf = 0; mf < 2; mf++) {
        #pragma unroll
        for (int h = 0; h < 2; h++) {
            int row = row0 + wm*32 + mf*16 + (lane>>2) + h*8;
            float lre = 0.f, lim = 0.f;
            if (MODE==0) { lre = Lam[2*row]; lim = Lam[2*row+1]; }
            #pragma unroll
            for (int nf = 0; nf < 4; nf++) {
                int col = col0 + wn*32 + nf*8 + (lane&3)*2;
                float vr0 = acc_r[mf][nf][h*2+0], vi0 = acc_i[mf][nf][h*2+0];
                float vr1 = acc_r[mf][nf][h*2+1], vi1 = acc_i[mf][nf][h*2+1];
                if (MODE==0) {
                    int l0 = col % 2049, l1 = (col+1) % 2049;
                    float om0 = 1.5339807878856412e-3f * (float)l0;
                    float om1 = 1.5339807878856412e-3f * (float)l1;
                    float dre = -lre;
                    float di0 = om0 - lim, di1 = om1 - lim;
                    float iv0 = 1.0f/(dre*dre + di0*di0);
                    float iv1 = 1.0f/(dre*dre + di1*di1);
                    float kr0 = dre*iv0, ki0 = -di0*iv0;
                    float kr1 = dre*iv1, ki1 = -di1*iv1;
                    float tr0 = vr0*kr0 - vi0*ki0, ti0 = vr0*ki0 + vi0*kr0;
                    float tr1 = vr1*kr1 - vi1*ki1, ti1 = vr1*ki1 + vi1*kr1;
                    // split W into bf16 planes, store pairs
                    size_t off = (size_t)row*NCOLP + col;
                    __nv_bfloat16 h0,l0b,h1,l1b;
                    split2(tr0,h0,l0b); split2(tr1,h1,l1b);
                    *reinterpret_cast<__nv_bfloat162*>(&g_Pb[0][off]) = __nv_bfloat162(h0,h1);
                    *reinterpret_cast<__nv_bfloat162*>(&g_Pb[1][off]) = __nv_bfloat162(l0b,l1b);
                    split2(ti0,h0,l0b); split2(ti1,h1,l1b);
                    *reinterpret_cast<__nv_bfloat162*>(&g_Pb[2][off]) = __nv_bfloat162(h0,h1);
                    *reinterpret_cast<__nv_bfloat162*>(&g_Pb[3][off]) = __nv_bfloat162(l0b,l1b);
                } else {
                    float4 o = make_float4(vr0, vi0, vr1, vi1);
                    *reinterpret_cast<float4*>(&g_Ys[(size_t)row*NCOLP + col]) = o;
                }
            }
        }
    }
}

// ---------------- inverse FFT + GELU ----------------------------------------
__global__ void __launch_bounds__(512) k_fft_inv(float* __restrict__ out) {
    extern __shared__ float2 sm[];
    float2* sa = sm; float2* sb = sm+4096; float2* tw = sm+8192;
    int r0 = blockIdx.x*2;
    int b = r0 >> 7, h0 = r0 & 127;
    const float2* in0 = g_Ys + (size_t)h0*NCOLP + b*LF;
    for (int k = threadIdx.x; k < LF; k += blockDim.x) {
        float2 y1 = in0[k];
        float2 y2 = in0[NCOLP+k];
        if (k == 0 || k == 2048) { y1.y = 0.f; y2.y = 0.f; }
        sa[k] = make_float2(y1.x - y2.y, y1.y + y2.x);
        if (k > 0 && k < 2048)
            sa[4096-k] = make_float2(y1.x + y2.y, y2.x - y1.y);
    }
    for (int k = threadIdx.x; k < 2048; k += blockDim.x) tw[k] = g_tw[k];
    __syncthreads();
    stockham12(sa, sb, tw, true);
    float* o0 = out + (size_t)r0*Ld;
    const float sc = 1.0f/4096.0f;
    for (int t = threadIdx.x; t < Ld; t += blockDim.x) {
        float v0 = sa[t].x*sc, v1 = sa[t].y*sc;
        o0[t]    = 0.5f*v0*(1.0f + erff(v0*0.70710678118654752f));
        o0[t+Ld] = 0.5f*v1*(1.0f + erff(v1*0.70710678118654752f));
    }
}

// ---------------- launch ----------------------------------------------------
extern "C" void kernel_launch(void* const* d_in, const int* in_sizes, int n_in,
                              void* d_out, int out_size) {
    (void)in_sizes; (void)n_in; (void)out_size;
    const float* u   = (const float*)d_in[0];
    const float* C2  = (const float*)d_in[1];
    const float* Bb2 = (const float*)d_in[2];
    const float* Dm  = (const float*)d_in[3];
    const float* Lam = (const float*)d_in[4];
    float* out = (float*)d_out;

    const int smem_fft = 10240 * (int)sizeof(float2);   // 80 KB
    cudaFuncSetAttribute(k_fft_fwd, cudaFuncAttributeMaxDynamicSharedMemorySize, smem_fft);
    cudaFuncSetAttribute(k_fft_inv, cudaFuncAttributeMaxDynamicSharedMemorySize, smem_fft);
    const int smem_gemm = 2*BUF_BF16*2;                 // 131072 B
    cudaFuncSetAttribute(k_cgemm_tc<0>, cudaFuncAttributeMaxDynamicSharedMemorySize, smem_gemm);
    cudaFuncSetAttribute(k_cgemm_tc<1>, cudaFuncAttributeMaxDynamicSharedMemorySize, smem_gemm);

    k_setup_tw<<<2, 1024>>>();
    k_fold1<<<384, 128>>>(C2, Bb2, Dm);
    k_fold2<<<128, 128>>>();
    k_splitA<<<(128*128 + 128*256 + 255)/256, 256>>>();
    k_fft_fwd<<<512, 512, smem_fft>>>(u);
    k_cgemm_tc<0><<<dim3(NCOLP/128, 2), 256, smem_gemm>>>(Lam);
    k_cgemm_tc<1><<<dim3(NCOLP/128, 2), 256, smem_gemm>>>(nullptr);
    k_fft_inv<<<512, 512, smem_fft>>>(out);
}

// round 5
// speedup vs baseline: 1.5595x; 1.0761x over previous
#include <cuda_runtime.h>
#include <cuda_bf16.h>
#include <cstdint>

#define BSZ   8
#define Hd    128
#define Ld    4096
#define LF    2049
#define NCOL  (BSZ*LF)      /* 16392 */
#define NCOLP 16512         /* multiple of 64 */
#define NT    64            /* cols per CTA */

// ---------------- scratch (device globals: allocation-free) ----------------
__device__ float2 g_twH[128];
__device__ float2 g_tw[2048];
__device__ float2 g_Bt[128*128];              // fp32 B~ [p][m]
__device__ float2 g_E [128*256];              // fp32 [C~|D~] row stride 256
__device__ float2 g_T [128*128];              // scratch
__device__ __nv_bfloat16 g_AB[6][128*128];    // split planes of B~   [p][m->k? no: [m][k]]
__device__ __nv_bfloat16 g_AE[6][128*256];    // split planes of [C~|D~]
__device__ __nv_bfloat16 g_Pb[4][128*NCOLP];  // Uhat split planes [k=p][n]
__device__ float2 g_Ys[128*NCOLP];            // spectral output (fp32)

__device__ __forceinline__ float2 cmulf(float2 a, float2 b) {
    return make_float2(a.x*b.x - a.y*b.y, a.x*b.y + a.y*b.x);
}
__device__ __forceinline__ void split2(float v, __nv_bfloat16& h, __nv_bfloat16& l) {
    h = __float2bfloat16(v);
    l = __float2bfloat16(v - __bfloat162float(h));
}

// ---------------- setup ----------------
__global__ void k_setup_tw() {
    int k = blockIdx.x*blockDim.x + threadIdx.x;
    if (k < 2048) { float s,c; sincospif(-(float)k/2048.0f,&s,&c); g_tw[k]=make_float2(c,s); }
    if (k < 128)  { float s,c; sincospif(-(float)k/64.0f,  &s,&c); g_twH[k]=make_float2(c,s); }
}

__global__ void k_fold1(const float* __restrict__ C2, const float* __restrict__ Bb2,
                        const float* __restrict__ Dm) {
    int bx = blockIdx.x, t = threadIdx.x;
    if (bx < 128) {
        int p = bx, m = t;
        float2 acc = make_float2(0.f,0.f);
        for (int q = 0; q < 128; q++) {
            float2 w = g_twH[(q*m)&127];
            float br = Bb2[(p*128+q)*2], bi = Bb2[(p*128+q)*2+1];
            acc.x += br*w.x - bi*w.y;
            acc.y += br*w.y + bi*w.x;
        }
        g_Bt[p*128+m] = acc;
    } else if (bx < 256) {
        int n = bx-128, p = t;
        float2 acc = make_float2(0.f,0.f);
        for (int h = 0; h < 128; h++) {
            float2 w = g_twH[(n*h)&127]; w.y = -w.y;
            float cr = C2[(h*128+p)*2], ci = C2[(h*128+p)*2+1];
            acc.x += cr*w.x - ci*w.y;
            acc.y += cr*w.y + ci*w.x;
        }
        g_E[n*256 + p] = make_float2(acc.x*(1.0f/128.0f), acc.y*(1.0f/128.0f));
    } else {
        int h = bx-256, m = t;
        float2 acc = make_float2(0.f,0.f);
        for (int q = 0; q < 128; q++) {
            float2 w = g_twH[(q*m)&127];
            float d = Dm[h*128+q];
            acc.x += d*w.x; acc.y += d*w.y;
        }
        g_T[h*128+m] = acc;
    }
}

__global__ void k_fold2() {
    int n = blockIdx.x, m = threadIdx.x;
    float2 acc = make_float2(0.f,0.f);
    for (int h = 0; h < 128; h++) {
        float2 w = g_twH[(n*h)&127]; w.y = -w.y;
        float2 tv = g_T[h*128+m];
        acc.x += tv.x*w.x - tv.y*w.y;
        acc.y += tv.x*w.y + tv.y*w.x;
    }
    g_E[n*256 + 128 + m] = make_float2(acc.x*(1.0f/128.0f), acc.y*(1.0f/128.0f));
}

// split A matrices into bf16 planes (ArH ArL AiH AiL -AiH -AiL)
__global__ void k_splitA() {
    int idx = blockIdx.x*blockDim.x + threadIdx.x;
    __nv_bfloat16 h, l;
    if (idx < 128*128) {
        float2 v = g_Bt[idx];
        split2(v.x,h,l);  g_AB[0][idx]=h; g_AB[1][idx]=l;
        split2(v.y,h,l);  g_AB[2][idx]=h; g_AB[3][idx]=l;
        split2(-v.y,h,l); g_AB[4][idx]=h; g_AB[5][idx]=l;
    }
    int idx2 = idx - 128*128;
    if (idx2 >= 0 && idx2 < 128*256) {
        float2 v = g_E[idx2];
        split2(v.x,h,l);  g_AE[0][idx2]=h; g_AE[1][idx2]=l;
        split2(v.y,h,l);  g_AE[2][idx2]=h; g_AE[3][idx2]=l;
        split2(-v.y,h,l); g_AE[4][idx2]=h; g_AE[5][idx2]=l;
    }
}

// ---------------- Stockham radix-2, N=4096 ----------------------------------
__device__ __forceinline__ void stockham12(float2* sa, float2* sb, const float2* tw, bool inv) {
    float2* src = sa; float2* dst = sb;
    #pragma unroll 1
    for (int st = 0; st < 12; st++) {
        int nh = 2048 >> st;
        int smask = (1<<st) - 1;
        for (int idx = threadIdx.x; idx < 2048; idx += blockDim.x) {
            int p = idx >> st;
            int q = idx & smask;
            float2 w = tw[p << st];
            if (inv) w.y = -w.y;
            float2 a = src[q + (p<<st)];
            float2 b = src[q + ((p+nh)<<st)];
            float2 sum = make_float2(a.x+b.x, a.y+b.y);
            float2 dif = make_float2(a.x-b.x, a.y-b.y);
            dst[q + ((2*p)<<st)]   = sum;
            dst[q + ((2*p+1)<<st)] = cmulf(dif, w);
        }
        __syncthreads();
        float2* tmp = src; src = dst; dst = tmp;
    }
}

// forward FFT: writes Uhat straight into bf16 split planes of g_Pb
__global__ void __launch_bounds__(512) k_fft_fwd(const float* __restrict__ u) {
    extern __shared__ float2 sm[];
    float2* sa = sm; float2* sb = sm+4096; float2* tw = sm+8192;
    int r0 = blockIdx.x*2;
    int b = r0 >> 7, h0 = r0 & 127;
    const float* u0 = u + (size_t)r0*Ld;
    for (int t = threadIdx.x; t < Ld; t += blockDim.x)
        sa[t] = make_float2(u0[t], u0[t+Ld]);
    for (int k = threadIdx.x; k < 2048; k += blockDim.x) tw[k] = g_tw[k];
    __syncthreads();
    stockham12(sa, sb, tw, false);
    size_t o1 = (size_t)h0*NCOLP + b*LF;
    size_t o2 = o1 + NCOLP;
    for (int k = threadIdx.x; k < LF; k += blockDim.x) {
        float2 zk = sa[k];
        float2 zn = sa[(4096-k)&4095];
        float2 x1 = make_float2(0.5f*(zk.x+zn.x), 0.5f*(zk.y-zn.y));
        float2 x2 = make_float2(0.5f*(zk.y+zn.y), 0.5f*(zn.x-zk.x));
        __nv_bfloat16 h, l;
        split2(x1.x,h,l); g_Pb[0][o1+k]=h; g_Pb[1][o1+k]=l;
        split2(x1.y,h,l); g_Pb[2][o1+k]=h; g_Pb[3][o1+k]=l;
        split2(x2.x,h,l); g_Pb[0][o2+k]=h; g_Pb[1][o2+k]=l;
        split2(x2.y,h,l); g_Pb[2][o2+k]=h; g_Pb[3][o2+k]=l;
    }
}

// ---------------- fused tensor-core pipeline --------------------------------
// One CTA per 64-column tile, M=128 (all rows).
//   GEMM1: W = K ⊙ (Bt · Uhat)   -> split to smem planes
//   GEMM2: Ys = [C~|D~] · [W ; Uhat]
// Uhat resident in smem (4 planes), W in smem (4 planes), A streamed in
// K=16 chunks (6 planes), double-buffered cp.async.

#define USTR 72
#define UPL  (128*USTR)          /* 9216 bf16 per U/W plane */
#define AKSTR 24
#define APL2 (128*AKSTR)         /* 3072 bf16 per A plane per buffer */
#define FUSED_SMEM ((8*UPL + 2*6*APL2) * 2)   /* 221184 bytes */

__device__ __forceinline__ uint32_t cvta_s(const void* p) {
    return (uint32_t)__cvta_generic_to_shared(p);
}
__device__ __forceinline__ void cp16(uint32_t s, const void* g) {
    asm volatile("cp.async.cg.shared.global [%0], [%1], 16;" :: "r"(s), "l"(g));
}
__device__ __forceinline__ void cp_commit() { asm volatile("cp.async.commit_group;"); }
__device__ __forceinline__ void cp_wait1()  { asm volatile("cp.async.wait_group 1;"); }
__device__ __forceinline__ void ldsm_x4(uint32_t& r0, uint32_t& r1, uint32_t& r2, uint32_t& r3,
                                        uint32_t addr) {
    asm volatile("ldmatrix.sync.aligned.m8n8.x4.shared.b16 {%0,%1,%2,%3}, [%4];"
                 : "=r"(r0), "=r"(r1), "=r"(r2), "=r"(r3) : "r"(addr));
}
__device__ __forceinline__ void ldsm_x4t(uint32_t& r0, uint32_t& r1, uint32_t& r2, uint32_t& r3,
                                         uint32_t addr) {
    asm volatile("ldmatrix.sync.aligned.m8n8.x4.trans.shared.b16 {%0,%1,%2,%3}, [%4];"
                 : "=r"(r0), "=r"(r1), "=r"(r2), "=r"(r3) : "r"(addr));
}
__device__ __forceinline__ void mma_bf16(float* c, const uint32_t* a, const uint32_t* b) {
    asm volatile("mma.sync.aligned.m16n8k16.row.col.f32.bf16.bf16.f32 "
                 "{%0,%1,%2,%3}, {%4,%5,%6,%7}, {%8,%9}, {%0,%1,%2,%3};"
                 : "+f"(c[0]), "+f"(c[1]), "+f"(c[2]), "+f"(c[3])
                 : "r"(a[0]), "r"(a[1]), "r"(a[2]), "r"(a[3]), "r"(b[0]), "r"(b[1]));
}

__global__ void __launch_bounds__(256, 1) k_fused(const float* __restrict__ Lam) {
    extern __shared__ __nv_bfloat16 smem[];
    __nv_bfloat16* Ub = smem;                 // 4 planes
    __nv_bfloat16* Wb = smem + 4*UPL;         // 4 planes
    __nv_bfloat16* Ab = smem + 8*UPL;         // 2 bufs x 6 planes

    const int tid  = threadIdx.x;
    const int warp = tid >> 5, lane = tid & 31;
    const int wm = warp & 3, wn = warp >> 2;     // 4 warps down M, 2 across N
    const int col0 = blockIdx.x*NT;
    const int l16 = lane & 15, lhi = (lane >> 4) << 3;

    float acc_r[2][4][4], acc_i[2][4][4];
    #pragma unroll
    for (int mf=0;mf<2;mf++)
        #pragma unroll
        for (int nf=0;nf<4;nf++)
            #pragma unroll
            for (int r=0;r<4;r++) { acc_r[mf][nf][r]=0.f; acc_i[mf][nf][r]=0.f; }

    // ---- one-time Uhat staging: 4 planes x 128 rows x 64 cols
    auto stageU = [&]() {
        #pragma unroll
        for (int i = 0; i < 16; i++) {
            int idx = tid + i*256;
            int pl = idx >> 10, rem = idx & 1023;
            int row = rem >> 3, c = rem & 7;
            cp16(cvta_s(Ub + pl*UPL + row*USTR + c*8),
                 g_Pb[pl] + (size_t)row*NCOLP + col0 + c*8);
        }
    };
    // ---- A chunk staging: chunk cc in 0..23 (0..7 = Bt, 8..23 = E)
    auto stageA = [&](int cc) {
        const __nv_bfloat16* Asrc;
        int ks, aplg, k0;
        if (cc < 8) { Asrc = g_AB[0]; ks = 128; aplg = 128*128; k0 = cc*16; }
        else        { Asrc = g_AE[0]; ks = 256; aplg = 128*256; k0 = (cc-8)*16; }
        __nv_bfloat16* dst = Ab + (cc&1)*(6*APL2);
        #pragma unroll
        for (int i = 0; i < 6; i++) {
            int idx = tid + i*256;
            int pl = idx >> 8, rem = idx & 255;
            int row = rem >> 1, c = rem & 1;
            cp16(cvta_s(dst + pl*APL2 + row*AKSTR + c*8),
                 Asrc + (size_t)pl*aplg + (size_t)row*ks + k0 + c*8);
        }
    };

    stageU(); stageA(0); cp_commit();
    stageA(1); cp_commit();

    #pragma unroll 1
    for (int c = 0; c < 24; c++) {
        if (c == 8) {
            // ---- GEMM1 epilogue: Cauchy, split W into smem planes, reset acc
            #pragma unroll
            for (int mf = 0; mf < 2; mf++) {
                #pragma unroll
                for (int h = 0; h < 2; h++) {
                    int row = wm*32 + mf*16 + (lane>>2) + h*8;
                    float lre = Lam[2*row], lim = Lam[2*row+1];
                    #pragma unroll
                    for (int nf = 0; nf < 4; nf++) {
                        int col = wn*32 + nf*8 + (lane&3)*2;
                        float vr0 = acc_r[mf][nf][h*2+0], vi0 = acc_i[mf][nf][h*2+0];
                        float vr1 = acc_r[mf][nf][h*2+1], vi1 = acc_i[mf][nf][h*2+1];
                        int gc = col0 + col;
                        int l0 = gc % 2049, l1 = (gc+1) % 2049;
                        float om0 = 1.5339807878856412e-3f * (float)l0;
                        float om1 = 1.5339807878856412e-3f * (float)l1;
                        float dre = -lre;
                        float di0 = om0 - lim, di1 = om1 - lim;
                        float iv0 = 1.0f/(dre*dre + di0*di0);
                        float iv1 = 1.0f/(dre*dre + di1*di1);
                        float kr0 = dre*iv0, ki0 = -di0*iv0;
                        float kr1 = dre*iv1, ki1 = -di1*iv1;
                        float tr0 = vr0*kr0 - vi0*ki0, ti0 = vr0*ki0 + vi0*kr0;
                        float tr1 = vr1*kr1 - vi1*ki1, ti1 = vr1*ki1 + vi1*kr1;
                        int off = row*USTR + col;
                        __nv_bfloat16 h0,l0b,h1,l1b;
                        split2(tr0,h0,l0b); split2(tr1,h1,l1b);
                        *reinterpret_cast<__nv_bfloat162*>(&Wb[0*UPL+off]) = __nv_bfloat162(h0,h1);
                        *reinterpret_cast<__nv_bfloat162*>(&Wb[1*UPL+off]) = __nv_bfloat162(l0b,l1b);
                        split2(ti0,h0,l0b); split2(ti1,h1,l1b);
                        *reinterpret_cast<__nv_bfloat162*>(&Wb[2*UPL+off]) = __nv_bfloat162(h0,h1);
                        *reinterpret_cast<__nv_bfloat162*>(&Wb[3*UPL+off]) = __nv_bfloat162(l0b,l1b);
                        acc_r[mf][nf][h*2+0]=0.f; acc_i[mf][nf][h*2+0]=0.f;
                        acc_r[mf][nf][h*2+1]=0.f; acc_i[mf][nf][h*2+1]=0.f;
                    }
                }
            }
        }
        cp_wait1();
        __syncthreads();

        // B source for this chunk
        const __nv_bfloat16* Bbase; int krow;
        if (c < 8)       { Bbase = Ub; krow = c*16; }
        else if (c < 16) { Bbase = Wb; krow = (c-8)*16; }
        else             { Bbase = Ub; krow = (c-16)*16; }
        const __nv_bfloat16* As = Ab + (c&1)*(6*APL2);

        uint32_t b[4][4][2];
        #pragma unroll
        for (int q = 0; q < 4; q++)
            #pragma unroll
            for (int np = 0; np < 2; np++) {
                uint32_t addr = cvta_s(Bbase + q*UPL + (krow + l16)*USTR
                                       + wn*32 + np*16 + lhi);
                ldsm_x4t(b[q][2*np][0], b[q][2*np][1], b[q][2*np+1][0], b[q][2*np+1][1], addr);
            }
        #pragma unroll
        for (int p = 0; p < 6; p++) {
            uint32_t a[2][4];
            #pragma unroll
            for (int mf = 0; mf < 2; mf++) {
                uint32_t addr = cvta_s(As + p*APL2 + (wm*32 + mf*16 + l16)*AKSTR + lhi);
                ldsm_x4(a[mf][0], a[mf][1], a[mf][2], a[mf][3], addr);
            }
            #pragma unroll
            for (int mf = 0; mf < 2; mf++)
                #pragma unroll
                for (int nf = 0; nf < 4; nf++) {
                    if (p == 0) {
                        mma_bf16(acc_r[mf][nf], a[mf], b[0][nf]);
                        mma_bf16(acc_r[mf][nf], a[mf], b[1][nf]);
                        mma_bf16(acc_i[mf][nf], a[mf], b[2][nf]);
                        mma_bf16(acc_i[mf][nf], a[mf], b[3][nf]);
                    } else if (p == 1) {
                        mma_bf16(acc_r[mf][nf], a[mf], b[0][nf]);
                        mma_bf16(acc_i[mf][nf], a[mf], b[2][nf]);
                    } else if (p == 2) {
                        mma_bf16(acc_i[mf][nf], a[mf], b[0][nf]);
                        mma_bf16(acc_i[mf][nf], a[mf], b[1][nf]);
                    } else if (p == 3) {
                        mma_bf16(acc_i[mf][nf], a[mf], b[0][nf]);
                    } else if (p == 4) {
                        mma_bf16(acc_r[mf][nf], a[mf], b[2][nf]);
                        mma_bf16(acc_r[mf][nf], a[mf], b[3][nf]);
                    } else {
                        mma_bf16(acc_r[mf][nf], a[mf], b[2][nf]);
                    }
                }
        }
        if (c + 2 < 24) stageA(c+2);
        cp_commit();
    }

    // ---- GEMM2 epilogue: write Ys (fp32)
    #pragma unroll
    for (int mf = 0; mf < 2; mf++) {
        #pragma unroll
        for (int h = 0; h < 2; h++) {
            int row = wm*32 + mf*16 + (lane>>2) + h*8;
            #pragma unroll
            for (int nf = 0; nf < 4; nf++) {
                int col = col0 + wn*32 + nf*8 + (lane&3)*2;
                float4 o = make_float4(acc_r[mf][nf][h*2+0], acc_i[mf][nf][h*2+0],
                                       acc_r[mf][nf][h*2+1], acc_i[mf][nf][h*2+1]);
                *reinterpret_cast<float4*>(&g_Ys[(size_t)row*NCOLP + col]) = o;
            }
        }
    }
}

// ---------------- inverse FFT + GELU ----------------------------------------
__global__ void __launch_bounds__(512) k_fft_inv(float* __restrict__ out) {
    extern __shared__ float2 sm[];
    float2* sa = sm; float2* sb = sm+4096; float2* tw = sm+8192;
    int r0 = blockIdx.x*2;
    int b = r0 >> 7, h0 = r0 & 127;
    const float2* in0 = g_Ys + (size_t)h0*NCOLP + b*LF;
    for (int k = threadIdx.x; k < LF; k += blockDim.x) {
        float2 y1 = in0[k];
        float2 y2 = in0[NCOLP+k];
        if (k == 0 || k == 2048) { y1.y = 0.f; y2.y = 0.f; }
        sa[k] = make_float2(y1.x - y2.y, y1.y + y2.x);
        if (k > 0 && k < 2048)
            sa[4096-k] = make_float2(y1.x + y2.y, y2.x - y1.y);
    }
    for (int k = threadIdx.x; k < 2048; k += blockDim.x) tw[k] = g_tw[k];
    __syncthreads();
    stockham12(sa, sb, tw, true);
    float* o0 = out + (size_t)r0*Ld;
    const float sc = 1.0f/4096.0f;
    for (int t = threadIdx.x; t < Ld; t += blockDim.x) {
        float v0 = sa[t].x*sc, v1 = sa[t].y*sc;
        o0[t]    = 0.5f*v0*(1.0f + erff(v0*0.70710678118654752f));
        o0[t+Ld] = 0.5f*v1*(1.0f + erff(v1*0.70710678118654752f));
    }
}

// ---------------- launch ----------------------------------------------------
extern "C" void kernel_launch(void* const* d_in, const int* in_sizes, int n_in,
                              void* d_out, int out_size) {
    (void)in_sizes; (void)n_in; (void)out_size;
    const float* u   = (const float*)d_in[0];
    const float* C2  = (const float*)d_in[1];
    const float* Bb2 = (const float*)d_in[2];
    const float* Dm  = (const float*)d_in[3];
    const float* Lam = (const float*)d_in[4];
    float* out = (float*)d_out;

    const int smem_fft = 10240 * (int)sizeof(float2);   // 80 KB
    cudaFuncSetAttribute(k_fft_fwd, cudaFuncAttributeMaxDynamicSharedMemorySize, smem_fft);
    cudaFuncSetAttribute(k_fft_inv, cudaFuncAttributeMaxDynamicSharedMemorySize, smem_fft);
    cudaFuncSetAttribute(k_fused,  cudaFuncAttributeMaxDynamicSharedMemorySize, FUSED_SMEM);

    k_setup_tw<<<2, 1024>>>();
    k_fold1<<<384, 128>>>(C2, Bb2, Dm);
    k_fold2<<<128, 128>>>();
    k_splitA<<<(128*128 + 128*256 + 255)/256, 256>>>();
    k_fft_fwd<<<512, 512, smem_fft>>>(u);
    k_fused<<<NCOLP/NT, 256, FUSED_SMEM>>>(Lam);
    k_fft_inv<<<512, 512, smem_fft>>>(out);
}